// round 3
// baseline (speedup 1.0000x reference)
#include <cuda_runtime.h>
#include <cstdint>
#include <cstddef>

#define T_STEPS 512
#define BATCH   64
#define DIMD    512
#define DIMH    512
#define N4H     2048   // 4 gates * H, packed as j' = hid*4 + gate
#define KDIM    512

// ---------------- device scratch (static, zero-init at module load) -------------
__device__ float g_Xproj[(size_t)T_STEPS * BATCH * N4H]; // 256 MB [t*B+b][j'] (x@Wx + b)
__device__ float g_hbuf[2][BATCH * DIMH];                // ping-pong h (step0 skips read)
__device__ unsigned long long g_tick = 0ULL;             // monotone ticket (never reset)
__device__ volatile unsigned long long g_rel = 0ULL;     // monotone release generation

// ---------------- f32x2 helpers --------------------------------------------------
struct __align__(16) ULL2 { unsigned long long x, y; };

static __device__ __forceinline__ unsigned long long pack2(float v) {
    unsigned long long r;
    unsigned u = __float_as_uint(v);
    asm("mov.b64 %0, {%1, %2};" : "=l"(r) : "r"(u), "r"(u));
    return r;
}
static __device__ __forceinline__ unsigned long long fma2(unsigned long long a,
                                                          unsigned long long b,
                                                          unsigned long long c) {
    unsigned long long d;
    asm("fma.rn.f32x2 %0, %1, %2, %3;" : "=l"(d) : "l"(a), "l"(b), "l"(c));
    return d;
}
static __device__ __forceinline__ unsigned long long add2(unsigned long long a,
                                                          unsigned long long b) {
    unsigned long long d;
    asm("add.rn.f32x2 %0, %1, %2;" : "=l"(d) : "l"(a), "l"(b));
    return d;
}
static __device__ __forceinline__ float lo32(unsigned long long v) {
    return __uint_as_float((unsigned)(v & 0xffffffffull));
}
static __device__ __forceinline__ float hi32(unsigned long long v) {
    return __uint_as_float((unsigned)(v >> 32));
}
static __device__ __forceinline__ float sigf(float x) {
    return __fdividef(1.0f, 1.0f + __expf(-x));
}
static __device__ __forceinline__ float tanh_(float x) {
    return 2.0f * sigf(2.0f * x) - 1.0f;
}

// ---------------- kernel 1: X-projection GEMM  [T*B,512] @ [512,2048] + bias ----
// Gathers B-tiles and bias directly from raw W_f/W_i/W_g/W_o (packed j' = c*4+g).
__global__ __launch_bounds__(256) void xproj_gemm(
        const float* __restrict__ A,
        const float* __restrict__ Wf, const float* __restrict__ bf,
        const float* __restrict__ Wi, const float* __restrict__ bi,
        const float* __restrict__ Wg, const float* __restrict__ bg,
        const float* __restrict__ Wo, const float* __restrict__ bo) {
    __shared__ float As[16 * 132];   // [k][m] transposed, pad 132
    __shared__ float Bs[16 * 64];    // [k][j'local]

    const int tid = threadIdx.x;
    const int tx = tid & 15;         // 4 cols
    const int ty = tid >> 4;         // 8 rows
    const int m0 = blockIdx.y * 128;
    const int n0 = blockIdx.x * 64;

    unsigned long long acc[8][2];
#pragma unroll
    for (int r = 0; r < 8; ++r) { acc[r][0] = 0ull; acc[r][1] = 0ull; }

    const int arow = tid >> 1;           // 0..127
    const int acol = (tid & 1) * 8;      // 0 or 8
    const int brow = tid >> 4;           // 0..15
    const int bcol = (tid & 15) * 4;     // multiple of 4 -> one c, gates f,i,g,o
    const int bc   = (n0 + bcol) >> 2;   // hidden col c for this thread's B quad

    for (int k0 = 0; k0 < KDIM; k0 += 16) {
        float4 av0 = *(const float4*)&A[(size_t)(m0 + arow) * DIMD + k0 + acol];
        float4 av1 = *(const float4*)&A[(size_t)(m0 + arow) * DIMD + k0 + acol + 4];
        size_t wofs = (size_t)(k0 + brow) * DIMH + bc;
        float4 bv;
        bv.x = Wf[wofs]; bv.y = Wi[wofs]; bv.z = Wg[wofs]; bv.w = Wo[wofs];
        __syncthreads();   // previous iter's reads done before overwrite
        As[(acol + 0) * 132 + arow] = av0.x;
        As[(acol + 1) * 132 + arow] = av0.y;
        As[(acol + 2) * 132 + arow] = av0.z;
        As[(acol + 3) * 132 + arow] = av0.w;
        As[(acol + 4) * 132 + arow] = av1.x;
        As[(acol + 5) * 132 + arow] = av1.y;
        As[(acol + 6) * 132 + arow] = av1.z;
        As[(acol + 7) * 132 + arow] = av1.w;
        *(float4*)&Bs[brow * 64 + bcol] = bv;
        __syncthreads();

#pragma unroll
        for (int kk = 0; kk < 16; ++kk) {
            float4 a0 = *(const float4*)&As[kk * 132 + ty * 8];
            float4 a1 = *(const float4*)&As[kk * 132 + ty * 8 + 4];
            ULL2 b2 = *(const ULL2*)&Bs[kk * 64 + tx * 4];
            float ar[8] = {a0.x, a0.y, a0.z, a0.w, a1.x, a1.y, a1.z, a1.w};
#pragma unroll
            for (int r = 0; r < 8; ++r) {
                unsigned long long pa = pack2(ar[r]);
                acc[r][0] = fma2(pa, b2.x, acc[r][0]);
                acc[r][1] = fma2(pa, b2.y, acc[r][1]);
            }
        }
    }

    float4 bias;
    bias.x = bf[bc]; bias.y = bi[bc]; bias.z = bg[bc]; bias.w = bo[bc];
#pragma unroll
    for (int r = 0; r < 8; ++r) {
        float4 o;
        o.x = lo32(acc[r][0]) + bias.x;
        o.y = hi32(acc[r][0]) + bias.y;
        o.z = lo32(acc[r][1]) + bias.z;
        o.w = hi32(acc[r][1]) + bias.w;
        *(float4*)&g_Xproj[(size_t)(m0 + ty * 8 + r) * N4H + n0 + tx * 4] = o;
    }
}

// ---------------- kernel 2: persistent recurrence (v3) ---------------------------
// 128 CTAs x 512 threads (16 warps = 4/SMSP).
// CTA r owns hidden units [r*4, r*4+4) -> packed gate cols [r*16, r*16+16).
// Warp w (0..15) owns k-slice [w*32, w*32+32). Thread (w, lane): batches lane,
// lane+32, all 16 cols. h read via __ldcg (L2). k-partials exchanged through
// padded smem; activations on warps 0-3. Grid sync = monotone ticket barrier.
// Step 0 skips the h-GEMV (h0 = 0), so no buffer init is needed.
//
// smem: Whs [512][16] = 32KB ; comb ULL[16][32][17] = 68KB  -> 100KB total.
#define REC_SMEM_BYTES (DIMH * 16 * 4 + 16 * 32 * 17 * 8)

__global__ __launch_bounds__(512, 1) void lstm_kernel(
        const float* __restrict__ Wf, const float* __restrict__ Wi,
        const float* __restrict__ Wg, const float* __restrict__ Wo,
        float* __restrict__ out, int out_size) {
    extern __shared__ float smem[];
    float* Whs = smem;                                                   // [512][16]
    unsigned long long* comb = (unsigned long long*)(smem + DIMH * 16);  // [16][32][17]

    const int r    = blockIdx.x;
    const int t    = threadIdx.x;
    const int w    = t >> 5;            // 0..15 : k-slice owner
    const int lane = t & 31;            // batches lane, lane+32

    // load Wh slice straight from raw weights: Whs[k*16 + cu*4 + g] = W_g[(512+k)*512 + r*4+cu]
    for (int i = t; i < DIMH * 16; i += 512) {
        int k = i >> 4;
        int cu = (i >> 2) & 3;
        int g = i & 3;
        const float* W = (g == 0) ? Wf : (g == 1) ? Wi : (g == 2) ? Wg : Wo;
        Whs[i] = W[(size_t)(DIMD + k) * DIMH + r * 4 + cu];
    }
    __syncthreads();

    float c0 = 0.0f, c1 = 0.0f;
    const size_t tail = (size_t)T_STEPS * BATCH * DIMH;
    const bool write_state = (size_t)out_size >= tail + 2u * BATCH * DIMH;

    for (int step = 0; step < T_STEPS; ++step) {
        // x-projection (DRAM) — issue early; independent of h
        float4 xpA, xpB;
        if (w < 4) {
            const float* xb = g_Xproj + ((size_t)step * BATCH + lane) * N4H + r * 16 + w * 4;
            xpA = __ldg((const float4*)xb);
            xpB = __ldg((const float4*)(xb + (size_t)32 * N4H));
        }

        if (step > 0) {
            const float* __restrict__ hsrc = g_hbuf[step & 1];
            const float* __restrict__ hrow0 = hsrc + (size_t)lane * DIMH + w * 32;
            const float* __restrict__ hrow1 = hsrc + (size_t)(lane + 32) * DIMH + w * 32;

            unsigned long long acc[16];
#pragma unroll
            for (int i = 0; i < 16; ++i) acc[i] = 0ull;

            // depth-2 LDG pipeline over 8 k-quads
            float4 pf0[2], pf1[2];
            pf0[0] = __ldcg((const float4*)(hrow0));
            pf1[0] = __ldcg((const float4*)(hrow1));
            pf0[1] = __ldcg((const float4*)(hrow0 + 4));
            pf1[1] = __ldcg((const float4*)(hrow1 + 4));

#pragma unroll
            for (int q = 0; q < 8; ++q) {
                float4 h0 = pf0[q & 1];
                float4 h1 = pf1[q & 1];
                if (q < 6) {
                    pf0[q & 1] = __ldcg((const float4*)(hrow0 + (q + 2) * 4));
                    pf1[q & 1] = __ldcg((const float4*)(hrow1 + (q + 2) * 4));
                }
                const float* wq = &Whs[(w * 32 + q * 4) * 16];
                float ha0[4] = {h0.x, h0.y, h0.z, h0.w};
                float ha1[4] = {h1.x, h1.y, h1.z, h1.w};
#pragma unroll
                for (int j = 0; j < 4; ++j) {
                    ULL2 wA = *(const ULL2*)(wq + j * 16);
                    ULL2 wB = *(const ULL2*)(wq + j * 16 + 4);
                    ULL2 wC = *(const ULL2*)(wq + j * 16 + 8);
                    ULL2 wD = *(const ULL2*)(wq + j * 16 + 12);
                    unsigned long long p0 = pack2(ha0[j]);
                    unsigned long long p1 = pack2(ha1[j]);
                    acc[0]  = fma2(p0, wA.x, acc[0]);
                    acc[1]  = fma2(p0, wA.y, acc[1]);
                    acc[2]  = fma2(p0, wB.x, acc[2]);
                    acc[3]  = fma2(p0, wB.y, acc[3]);
                    acc[4]  = fma2(p0, wC.x, acc[4]);
                    acc[5]  = fma2(p0, wC.y, acc[5]);
                    acc[6]  = fma2(p0, wD.x, acc[6]);
                    acc[7]  = fma2(p0, wD.y, acc[7]);
                    acc[8]  = fma2(p1, wA.x, acc[8]);
                    acc[9]  = fma2(p1, wA.y, acc[9]);
                    acc[10] = fma2(p1, wB.x, acc[10]);
                    acc[11] = fma2(p1, wB.y, acc[11]);
                    acc[12] = fma2(p1, wC.x, acc[12]);
                    acc[13] = fma2(p1, wC.y, acc[13]);
                    acc[14] = fma2(p1, wD.x, acc[14]);
                    acc[15] = fma2(p1, wD.y, acc[15]);
                }
            }

            // exchange k-partials
            unsigned long long* cw = comb + ((size_t)w * 32 + lane) * 17;
#pragma unroll
            for (int i = 0; i < 16; ++i) cw[i] = acc[i];
            __syncthreads();
        }

        // warps 0-3: unit u = w. Sum 16 k-partials, gates, write h/out.
        if (w < 4) {
            const int u = w;
            unsigned long long s0 = 0, s1 = 0, s2 = 0, s3 = 0;
            if (step > 0) {
#pragma unroll
                for (int kh = 0; kh < 16; ++kh) {
                    const unsigned long long* cr = comb + ((size_t)kh * 32 + lane) * 17;
                    s0 = add2(s0, cr[u * 2]);
                    s1 = add2(s1, cr[u * 2 + 1]);
                    s2 = add2(s2, cr[8 + u * 2]);
                    s3 = add2(s3, cr[8 + u * 2 + 1]);
                }
            }
            float zf0 = lo32(s0) + xpA.x, zi0 = hi32(s0) + xpA.y;
            float zg0 = lo32(s1) + xpA.z, zo0 = hi32(s1) + xpA.w;
            float zf1 = lo32(s2) + xpB.x, zi1 = hi32(s2) + xpB.y;
            float zg1 = lo32(s3) + xpB.z, zo1 = hi32(s3) + xpB.w;

            c0 = sigf(zf0) * c0 + sigf(zi0) * tanh_(zg0);
            c1 = sigf(zf1) * c1 + sigf(zi1) * tanh_(zg1);
            float h0v = sigf(zo0) * tanh_(c0);
            float h1v = sigf(zo1) * tanh_(c1);

            const int hid = r * 4 + u;
            float* hnxt = g_hbuf[(step + 1) & 1];
            hnxt[lane * DIMH + hid]        = h0v;
            hnxt[(lane + 32) * DIMH + hid] = h1v;
            out[((size_t)step * BATCH + lane) * DIMH + hid]      = h0v;
            out[((size_t)step * BATCH + lane + 32) * DIMH + hid] = h1v;
            if (step == T_STEPS - 1 && write_state) {
                out[tail + (size_t)lane * DIMH + hid]        = h0v;
                out[tail + (size_t)(lane + 32) * DIMH + hid] = h1v;
                out[tail + (size_t)BATCH * DIMH + (size_t)lane * DIMH + hid]        = c0;
                out[tail + (size_t)BATCH * DIMH + (size_t)(lane + 32) * DIMH + hid] = c1;
            }
        }

        // ---- monotone ticket grid barrier (no init required, replay-safe) ----
        __threadfence();
        __syncthreads();
        if (t == 0) {
            unsigned long long tk = atomicAdd(&g_tick, 1ULL);
            unsigned long long gen = tk >> 7;           // /128 CTAs
            if ((tk & 127ULL) == 127ULL) {
                __threadfence();
                g_rel = gen + 1ULL;
            } else {
                while (g_rel <= gen) { }
                __threadfence();
            }
        }
        __syncthreads();
    }
}

// ---------------- launch ----------------------------------------------------------
extern "C" void kernel_launch(void* const* d_in, const int* in_sizes, int n_in,
                              void* d_out, int out_size) {
    const float* inputs = (const float*)d_in[0];
    const float* Wf = (const float*)d_in[1];
    const float* bf = (const float*)d_in[2];
    const float* Wi = (const float*)d_in[3];
    const float* bi = (const float*)d_in[4];
    const float* Wg = (const float*)d_in[5];
    const float* bg = (const float*)d_in[6];
    const float* Wo = (const float*)d_in[7];
    const float* bo = (const float*)d_in[8];

    dim3 g1(N4H / 64, (T_STEPS * BATCH) / 128);   // (32, 256)
    xproj_gemm<<<g1, 256>>>(inputs, Wf, bf, Wi, bi, Wg, bg, Wo, bo);

    const int rec_smem = REC_SMEM_BYTES;   // 32768 + 69632 = 102400 B
    cudaFuncSetAttribute(lstm_kernel, cudaFuncAttributeMaxDynamicSharedMemorySize, rec_smem);
    lstm_kernel<<<128, 512, rec_smem>>>(Wf, Wi, Wg, Wo, (float*)d_out, out_size);
}

// round 4
// speedup vs baseline: 1.4360x; 1.4360x over previous
#include <cuda_runtime.h>
#include <cstdint>
#include <cstddef>

#define T_STEPS 512
#define BATCH   64
#define DIMD    512
#define DIMH    512
#define N4H     2048   // 4 gates * H, packed as j' = hid*4 + gate
#define KDIM    512
#define HB      (DIMH * BATCH)   // 32768 floats per step slice

// ---------------- device scratch (static, zero-init at module load) -------------
__device__ float g_Xproj[(size_t)T_STEPS * BATCH * N4H]; // 256 MB [t*B+b][j'] (x@Wx + b)
__device__ float g_outT[(size_t)T_STEPS * HB];           // 64 MB [t][hid][b] (h history)
__device__ float g_cT[HB];                               // final c, [hid][b]
__device__ unsigned long long g_tick = 0ULL;             // monotone ticket (never reset)
__device__ volatile unsigned long long g_rel = 0ULL;     // monotone release generation

// ---------------- f32x2 helpers --------------------------------------------------
struct __align__(16) ULL2 { unsigned long long x, y; };

static __device__ __forceinline__ unsigned long long pack2(float v) {
    unsigned long long r;
    unsigned u = __float_as_uint(v);
    asm("mov.b64 %0, {%1, %2};" : "=l"(r) : "r"(u), "r"(u));
    return r;
}
static __device__ __forceinline__ unsigned long long fma2(unsigned long long a,
                                                          unsigned long long b,
                                                          unsigned long long c) {
    unsigned long long d;
    asm("fma.rn.f32x2 %0, %1, %2, %3;" : "=l"(d) : "l"(a), "l"(b), "l"(c));
    return d;
}
static __device__ __forceinline__ unsigned long long add2(unsigned long long a,
                                                          unsigned long long b) {
    unsigned long long d;
    asm("add.rn.f32x2 %0, %1, %2;" : "=l"(d) : "l"(a), "l"(b));
    return d;
}
static __device__ __forceinline__ float lo32(unsigned long long v) {
    return __uint_as_float((unsigned)(v & 0xffffffffull));
}
static __device__ __forceinline__ float hi32(unsigned long long v) {
    return __uint_as_float((unsigned)(v >> 32));
}
static __device__ __forceinline__ float sigf(float x) {
    return __fdividef(1.0f, 1.0f + __expf(-x));
}
static __device__ __forceinline__ float tanh_(float x) {
    return 2.0f * sigf(2.0f * x) - 1.0f;
}

// ---------------- kernel 1: X-projection GEMM  [T*B,512] @ [512,2048] + bias ----
__global__ __launch_bounds__(256) void xproj_gemm(
        const float* __restrict__ A,
        const float* __restrict__ Wf, const float* __restrict__ bf,
        const float* __restrict__ Wi, const float* __restrict__ bi,
        const float* __restrict__ Wg, const float* __restrict__ bg,
        const float* __restrict__ Wo, const float* __restrict__ bo) {
    __shared__ float As[16 * 132];   // [k][m] transposed, pad 132
    __shared__ float Bs[16 * 64];    // [k][j'local]

    const int tid = threadIdx.x;
    const int tx = tid & 15;
    const int ty = tid >> 4;
    const int m0 = blockIdx.y * 128;
    const int n0 = blockIdx.x * 64;

    unsigned long long acc[8][2];
#pragma unroll
    for (int r = 0; r < 8; ++r) { acc[r][0] = 0ull; acc[r][1] = 0ull; }

    const int arow = tid >> 1;
    const int acol = (tid & 1) * 8;
    const int brow = tid >> 4;
    const int bcol = (tid & 15) * 4;     // one c, gates f,i,g,o
    const int bc   = (n0 + bcol) >> 2;

    for (int k0 = 0; k0 < KDIM; k0 += 16) {
        float4 av0 = *(const float4*)&A[(size_t)(m0 + arow) * DIMD + k0 + acol];
        float4 av1 = *(const float4*)&A[(size_t)(m0 + arow) * DIMD + k0 + acol + 4];
        size_t wofs = (size_t)(k0 + brow) * DIMH + bc;
        float4 bv;
        bv.x = Wf[wofs]; bv.y = Wi[wofs]; bv.z = Wg[wofs]; bv.w = Wo[wofs];
        __syncthreads();
        As[(acol + 0) * 132 + arow] = av0.x;
        As[(acol + 1) * 132 + arow] = av0.y;
        As[(acol + 2) * 132 + arow] = av0.z;
        As[(acol + 3) * 132 + arow] = av0.w;
        As[(acol + 4) * 132 + arow] = av1.x;
        As[(acol + 5) * 132 + arow] = av1.y;
        As[(acol + 6) * 132 + arow] = av1.z;
        As[(acol + 7) * 132 + arow] = av1.w;
        *(float4*)&Bs[brow * 64 + bcol] = bv;
        __syncthreads();

#pragma unroll
        for (int kk = 0; kk < 16; ++kk) {
            float4 a0 = *(const float4*)&As[kk * 132 + ty * 8];
            float4 a1 = *(const float4*)&As[kk * 132 + ty * 8 + 4];
            ULL2 b2 = *(const ULL2*)&Bs[kk * 64 + tx * 4];
            float ar[8] = {a0.x, a0.y, a0.z, a0.w, a1.x, a1.y, a1.z, a1.w};
#pragma unroll
            for (int r = 0; r < 8; ++r) {
                unsigned long long pa = pack2(ar[r]);
                acc[r][0] = fma2(pa, b2.x, acc[r][0]);
                acc[r][1] = fma2(pa, b2.y, acc[r][1]);
            }
        }
    }

    float4 bias;
    bias.x = bf[bc]; bias.y = bi[bc]; bias.z = bg[bc]; bias.w = bo[bc];
#pragma unroll
    for (int r = 0; r < 8; ++r) {
        float4 o;
        o.x = lo32(acc[r][0]) + bias.x;
        o.y = hi32(acc[r][0]) + bias.y;
        o.z = lo32(acc[r][1]) + bias.z;
        o.w = hi32(acc[r][1]) + bias.w;
        *(float4*)&g_Xproj[(size_t)(m0 + ty * 8 + r) * N4H + n0 + tx * 4] = o;
    }
}

// ---------------- kernel 2: persistent recurrence (v4, transposed h) -------------
// 128 CTAs x 512 threads. CTA r: hidden units [r*4, r*4+4) -> gate cols [r*16,+16).
// Warp w owns k-slice [w*32, +32). Thread (w, lane): batches lane, lane+32, 16 cols.
// h lives in g_outT[t][hid][b]  -> all h reads/writes COALESCED (1 line / warp-load).
// k-partials exchanged via padded smem; activations on warps 0-3; ticket barrier.
#define REC_SMEM_BYTES (DIMH * 16 * 4 + 16 * 32 * 17 * 8)   // 32768 + 69632 = 102400

__global__ __launch_bounds__(512, 1) void lstm_kernel(
        const float* __restrict__ Wf, const float* __restrict__ Wi,
        const float* __restrict__ Wg, const float* __restrict__ Wo) {
    extern __shared__ float smem[];
    float* Whs = smem;                                                   // [512][16]
    unsigned long long* comb = (unsigned long long*)(smem + DIMH * 16);  // [16][32][17]

    const int r    = blockIdx.x;
    const int t    = threadIdx.x;
    const int w    = t >> 5;
    const int lane = t & 31;

    // Whs[k*16 + cu*4 + g] = W_g[(512+k)*512 + r*4+cu]
    for (int i = t; i < DIMH * 16; i += 512) {
        int k = i >> 4;
        int cu = (i >> 2) & 3;
        int g = i & 3;
        const float* W = (g == 0) ? Wf : (g == 1) ? Wi : (g == 2) ? Wg : Wo;
        Whs[i] = W[(size_t)(DIMD + k) * DIMH + r * 4 + cu];
    }
    __syncthreads();

    float c0 = 0.0f, c1 = 0.0f;

    for (int step = 0; step < T_STEPS; ++step) {
        // x-projection loads (independent of h; long latency hidden under GEMV)
        float4 xpA, xpB;
        if (w < 4) {
            const float* xb = g_Xproj + ((size_t)step * BATCH + lane) * N4H + r * 16 + w * 4;
            xpA = __ldg((const float4*)xb);
            xpB = __ldg((const float4*)(xb + (size_t)32 * N4H));
        }

        if (step > 0) {
            // h slice for this warp: g_outT[(step-1)][w*32 + q][b], b = lane / lane+32
            const float* __restrict__ hb = g_outT + (size_t)(step - 1) * HB + (w * 32) * BATCH;

            unsigned long long acc[16];
#pragma unroll
            for (int i = 0; i < 16; ++i) acc[i] = 0ull;

            float cur0[4], cur1[4], nxt0[4], nxt1[4];
#pragma unroll
            for (int i = 0; i < 4; ++i) {
                cur0[i] = __ldcg(hb + i * BATCH + lane);
                cur1[i] = __ldcg(hb + i * BATCH + lane + 32);
            }

#pragma unroll
            for (int qb = 0; qb < 8; ++qb) {
                if (qb < 7) {
#pragma unroll
                    for (int i = 0; i < 4; ++i) {
                        nxt0[i] = __ldcg(hb + ((qb + 1) * 4 + i) * BATCH + lane);
                        nxt1[i] = __ldcg(hb + ((qb + 1) * 4 + i) * BATCH + lane + 32);
                    }
                }
#pragma unroll
                for (int i = 0; i < 4; ++i) {
                    const float* wq = &Whs[(w * 32 + qb * 4 + i) * 16];
                    ULL2 wA = *(const ULL2*)(wq);
                    ULL2 wB = *(const ULL2*)(wq + 4);
                    ULL2 wC = *(const ULL2*)(wq + 8);
                    ULL2 wD = *(const ULL2*)(wq + 12);
                    unsigned long long p0 = pack2(cur0[i]);
                    unsigned long long p1 = pack2(cur1[i]);
                    acc[0]  = fma2(p0, wA.x, acc[0]);
                    acc[1]  = fma2(p0, wA.y, acc[1]);
                    acc[2]  = fma2(p0, wB.x, acc[2]);
                    acc[3]  = fma2(p0, wB.y, acc[3]);
                    acc[4]  = fma2(p0, wC.x, acc[4]);
                    acc[5]  = fma2(p0, wC.y, acc[5]);
                    acc[6]  = fma2(p0, wD.x, acc[6]);
                    acc[7]  = fma2(p0, wD.y, acc[7]);
                    acc[8]  = fma2(p1, wA.x, acc[8]);
                    acc[9]  = fma2(p1, wA.y, acc[9]);
                    acc[10] = fma2(p1, wB.x, acc[10]);
                    acc[11] = fma2(p1, wB.y, acc[11]);
                    acc[12] = fma2(p1, wC.x, acc[12]);
                    acc[13] = fma2(p1, wC.y, acc[13]);
                    acc[14] = fma2(p1, wD.x, acc[14]);
                    acc[15] = fma2(p1, wD.y, acc[15]);
                }
#pragma unroll
                for (int i = 0; i < 4; ++i) { cur0[i] = nxt0[i]; cur1[i] = nxt1[i]; }
            }

            unsigned long long* cw = comb + ((size_t)w * 32 + lane) * 17;
#pragma unroll
            for (int i = 0; i < 16; ++i) cw[i] = acc[i];
            __syncthreads();
        }

        if (w < 4) {
            const int u = w;
            unsigned long long s0 = 0, s1 = 0, s2 = 0, s3 = 0;
            if (step > 0) {
#pragma unroll
                for (int kh = 0; kh < 16; ++kh) {
                    const unsigned long long* cr = comb + ((size_t)kh * 32 + lane) * 17;
                    s0 = add2(s0, cr[u * 2]);
                    s1 = add2(s1, cr[u * 2 + 1]);
                    s2 = add2(s2, cr[8 + u * 2]);
                    s3 = add2(s3, cr[8 + u * 2 + 1]);
                }
            }
            float zf0 = lo32(s0) + xpA.x, zi0 = hi32(s0) + xpA.y;
            float zg0 = lo32(s1) + xpA.z, zo0 = hi32(s1) + xpA.w;
            float zf1 = lo32(s2) + xpB.x, zi1 = hi32(s2) + xpB.y;
            float zg1 = lo32(s3) + xpB.z, zo1 = hi32(s3) + xpB.w;

            c0 = sigf(zf0) * c0 + sigf(zi0) * tanh_(zg0);
            c1 = sigf(zf1) * c1 + sigf(zi1) * tanh_(zg1);
            float h0v = sigf(zo0) * tanh_(c0);
            float h1v = sigf(zo1) * tanh_(c1);

            const int hid = r * 4 + u;
            float* hdst = g_outT + (size_t)step * HB + hid * BATCH;   // coalesced
            hdst[lane]      = h0v;
            hdst[lane + 32] = h1v;
            if (step == T_STEPS - 1) {
                g_cT[hid * BATCH + lane]      = c0;
                g_cT[hid * BATCH + lane + 32] = c1;
            }
        }

        // ---- monotone ticket grid barrier ----
        __threadfence();
        __syncthreads();
        if (t == 0) {
            unsigned long long tk = atomicAdd(&g_tick, 1ULL);
            unsigned long long gen = tk >> 7;           // /128 CTAs
            if ((tk & 127ULL) == 127ULL) {
                __threadfence();
                g_rel = gen + 1ULL;
            } else {
                while (g_rel <= gen) { }
                __threadfence();
            }
        }
        __syncthreads();
    }
}

// ---------------- kernel 3: transpose outT -> out (+ hx/cx tail) -----------------
// out[t][b][h] = g_outT[t][h][b]. Block: 256 thr, tile 32h x 64b, smem pad 65.
__global__ __launch_bounds__(256) void transpose_out(float* __restrict__ out, int out_size) {
    __shared__ float tile[32][65];
    const int tblk = blockIdx.x;         // 0..512 ; 512 == tail (hx, cx)
    const int h0   = blockIdx.y * 32;
    const int tx   = threadIdx.x;        // 0..63 (batch on load)
    const int ty   = threadIdx.y;        // 0..3
    const int tid  = ty * 64 + tx;
    const int wh   = tid & 31;           // h within tile (on store)
    const int wb0  = tid >> 5;           // 0..7

    const size_t tail = (size_t)T_STEPS * BATCH * DIMH;
    const bool write_state = (size_t)out_size >= tail + 2u * BATCH * DIMH;

    if (tblk < T_STEPS) {
        const float* src = g_outT + (size_t)tblk * HB;
#pragma unroll
        for (int i = 0; i < 8; ++i) {
            int hl = i * 4 + ty;
            tile[hl][tx] = src[(size_t)(h0 + hl) * BATCH + tx];
        }
        __syncthreads();
        float* dst = out + (size_t)tblk * BATCH * DIMH;
#pragma unroll
        for (int j = 0; j < 8; ++j) {
            int b = wb0 + j * 8;
            dst[(size_t)b * DIMH + h0 + wh] = tile[wh][b];
        }
    } else if (write_state) {
        // hx tail from outT[last step]
        const float* src = g_outT + (size_t)(T_STEPS - 1) * HB;
#pragma unroll
        for (int i = 0; i < 8; ++i) {
            int hl = i * 4 + ty;
            tile[hl][tx] = src[(size_t)(h0 + hl) * BATCH + tx];
        }
        __syncthreads();
        float* dst = out + tail;
#pragma unroll
        for (int j = 0; j < 8; ++j) {
            int b = wb0 + j * 8;
            dst[(size_t)b * DIMH + h0 + wh] = tile[wh][b];
        }
        __syncthreads();
        // cx tail from g_cT
#pragma unroll
        for (int i = 0; i < 8; ++i) {
            int hl = i * 4 + ty;
            tile[hl][tx] = g_cT[(size_t)(h0 + hl) * BATCH + tx];
        }
        __syncthreads();
        float* dst2 = out + tail + (size_t)BATCH * DIMH;
#pragma unroll
        for (int j = 0; j < 8; ++j) {
            int b = wb0 + j * 8;
            dst2[(size_t)b * DIMH + h0 + wh] = tile[wh][b];
        }
    }
}

// ---------------- launch ----------------------------------------------------------
extern "C" void kernel_launch(void* const* d_in, const int* in_sizes, int n_in,
                              void* d_out, int out_size) {
    const float* inputs = (const float*)d_in[0];
    const float* Wf = (const float*)d_in[1];
    const float* bf = (const float*)d_in[2];
    const float* Wi = (const float*)d_in[3];
    const float* bi = (const float*)d_in[4];
    const float* Wg = (const float*)d_in[5];
    const float* bg = (const float*)d_in[6];
    const float* Wo = (const float*)d_in[7];
    const float* bo = (const float*)d_in[8];

    dim3 g1(N4H / 64, (T_STEPS * BATCH) / 128);   // (32, 256)
    xproj_gemm<<<g1, 256>>>(inputs, Wf, bf, Wi, bi, Wg, bg, Wo, bo);

    cudaFuncSetAttribute(lstm_kernel, cudaFuncAttributeMaxDynamicSharedMemorySize, REC_SMEM_BYTES);
    lstm_kernel<<<128, 512, REC_SMEM_BYTES>>>(Wf, Wi, Wg, Wo);

    transpose_out<<<dim3(T_STEPS + 1, DIMH / 32), dim3(64, 4)>>>((float*)d_out, out_size);
}

// round 5
// speedup vs baseline: 1.4456x; 1.0067x over previous
#include <cuda_runtime.h>
#include <cstdint>
#include <cstddef>

#define T_STEPS 512
#define BATCH   64
#define DIMD    512
#define DIMH    512
#define N4H     2048   // 4 gates * H, packed as j' = hid*4 + gate
#define KDIM    512
#define HB      (DIMH * BATCH)   // 32768 floats per step slice

// ---------------- device scratch (static, zero-init at module load) -------------
__device__ float g_Xproj[(size_t)T_STEPS * BATCH * N4H]; // 256 MB [t*B+b][j'] (x@Wx + b)
__device__ float g_outT[(size_t)T_STEPS * HB];           // 64 MB [t][hid][b] (h history)
__device__ float g_cT[HB];                               // final c, [hid][b]
__device__ unsigned long long g_tick = 0ULL;             // monotone ticket (never reset)
__device__ volatile unsigned long long g_rel = 0ULL;     // monotone release generation

// ---------------- f32x2 helpers --------------------------------------------------
struct __align__(16) ULL2 { unsigned long long x, y; };

static __device__ __forceinline__ unsigned long long pack2(float v) {
    unsigned long long r;
    unsigned u = __float_as_uint(v);
    asm("mov.b64 %0, {%1, %2};" : "=l"(r) : "r"(u), "r"(u));
    return r;
}
static __device__ __forceinline__ unsigned long long fma2(unsigned long long a,
                                                          unsigned long long b,
                                                          unsigned long long c) {
    unsigned long long d;
    asm("fma.rn.f32x2 %0, %1, %2, %3;" : "=l"(d) : "l"(a), "l"(b), "l"(c));
    return d;
}
static __device__ __forceinline__ unsigned long long add2(unsigned long long a,
                                                          unsigned long long b) {
    unsigned long long d;
    asm("add.rn.f32x2 %0, %1, %2;" : "=l"(d) : "l"(a), "l"(b));
    return d;
}
static __device__ __forceinline__ float lo32(unsigned long long v) {
    return __uint_as_float((unsigned)(v & 0xffffffffull));
}
static __device__ __forceinline__ float hi32(unsigned long long v) {
    return __uint_as_float((unsigned)(v >> 32));
}
static __device__ __forceinline__ float sigf(float x) {
    return __fdividef(1.0f, 1.0f + __expf(-x));
}
static __device__ __forceinline__ float tanh_(float x) {
    return 2.0f * sigf(2.0f * x) - 1.0f;
}

// ---------------- kernel 1: X-projection GEMM (double-buffered, 1 sync/tile) -----
__global__ __launch_bounds__(256) void xproj_gemm(
        const float* __restrict__ A,
        const float* __restrict__ Wf, const float* __restrict__ bf,
        const float* __restrict__ Wi, const float* __restrict__ bi,
        const float* __restrict__ Wg, const float* __restrict__ bg,
        const float* __restrict__ Wo, const float* __restrict__ bo) {
    __shared__ float As[2][16 * 132];   // [k][m] transposed, pad 132
    __shared__ float Bs[2][16 * 64];    // [k][j'local]

    const int tid = threadIdx.x;
    const int tx = tid & 15;
    const int ty = tid >> 4;
    const int m0 = blockIdx.y * 128;
    const int n0 = blockIdx.x * 64;

    unsigned long long acc[8][2];
#pragma unroll
    for (int r = 0; r < 8; ++r) { acc[r][0] = 0ull; acc[r][1] = 0ull; }

    const int arow = tid >> 1;
    const int acol = (tid & 1) * 8;
    const int brow = tid >> 4;
    const int bcol = (tid & 15) * 4;     // one c, gates f,i,g,o
    const int bc   = (n0 + bcol) >> 2;

    // prologue: load + store tile 0
    float4 av0 = *(const float4*)&A[(size_t)(m0 + arow) * DIMD + acol];
    float4 av1 = *(const float4*)&A[(size_t)(m0 + arow) * DIMD + acol + 4];
    float4 bv;
    {
        size_t wofs = (size_t)brow * DIMH + bc;
        bv.x = Wf[wofs]; bv.y = Wi[wofs]; bv.z = Wg[wofs]; bv.w = Wo[wofs];
    }
    {
        float* Ap = As[0];
        Ap[(acol + 0) * 132 + arow] = av0.x;
        Ap[(acol + 1) * 132 + arow] = av0.y;
        Ap[(acol + 2) * 132 + arow] = av0.z;
        Ap[(acol + 3) * 132 + arow] = av0.w;
        Ap[(acol + 4) * 132 + arow] = av1.x;
        Ap[(acol + 5) * 132 + arow] = av1.y;
        Ap[(acol + 6) * 132 + arow] = av1.z;
        Ap[(acol + 7) * 132 + arow] = av1.w;
        *(float4*)&Bs[0][brow * 64 + bcol] = bv;
    }
    __syncthreads();

    int p = 0;
    for (int k0 = 0; k0 < KDIM; k0 += 16) {
        const bool more = (k0 + 16) < KDIM;
        if (more) {
            av0 = *(const float4*)&A[(size_t)(m0 + arow) * DIMD + k0 + 16 + acol];
            av1 = *(const float4*)&A[(size_t)(m0 + arow) * DIMD + k0 + 16 + acol + 4];
            size_t wofs = (size_t)(k0 + 16 + brow) * DIMH + bc;
            bv.x = Wf[wofs]; bv.y = Wi[wofs]; bv.z = Wg[wofs]; bv.w = Wo[wofs];
        }

        const float* Ap = As[p];
        const float* Bp = Bs[p];
#pragma unroll
        for (int kk = 0; kk < 16; ++kk) {
            float4 a0 = *(const float4*)&Ap[kk * 132 + ty * 8];
            float4 a1 = *(const float4*)&Ap[kk * 132 + ty * 8 + 4];
            ULL2 b2 = *(const ULL2*)&Bp[kk * 64 + tx * 4];
            float ar[8] = {a0.x, a0.y, a0.z, a0.w, a1.x, a1.y, a1.z, a1.w};
#pragma unroll
            for (int r = 0; r < 8; ++r) {
                unsigned long long pa = pack2(ar[r]);
                acc[r][0] = fma2(pa, b2.x, acc[r][0]);
                acc[r][1] = fma2(pa, b2.y, acc[r][1]);
            }
        }

        if (more) {
            float* An = As[p ^ 1];
            An[(acol + 0) * 132 + arow] = av0.x;
            An[(acol + 1) * 132 + arow] = av0.y;
            An[(acol + 2) * 132 + arow] = av0.z;
            An[(acol + 3) * 132 + arow] = av0.w;
            An[(acol + 4) * 132 + arow] = av1.x;
            An[(acol + 5) * 132 + arow] = av1.y;
            An[(acol + 6) * 132 + arow] = av1.z;
            An[(acol + 7) * 132 + arow] = av1.w;
            *(float4*)&Bs[p ^ 1][brow * 64 + bcol] = bv;
            __syncthreads();
        }
        p ^= 1;
    }

    float4 bias;
    bias.x = bf[bc]; bias.y = bi[bc]; bias.z = bg[bc]; bias.w = bo[bc];
#pragma unroll
    for (int r = 0; r < 8; ++r) {
        float4 o;
        o.x = lo32(acc[r][0]) + bias.x;
        o.y = hi32(acc[r][0]) + bias.y;
        o.z = lo32(acc[r][1]) + bias.z;
        o.w = hi32(acc[r][1]) + bias.w;
        *(float4*)&g_Xproj[(size_t)(m0 + ty * 8 + r) * N4H + n0 + tx * 4] = o;
    }
}

// ---------------- kernel 2: persistent recurrence (v5) ---------------------------
// 128 CTAs x 512 threads. CTA r: hidden units [r*4,+4) -> gate cols [r*16,+16).
// Warp w owns k-slice [w*32,+32). h in g_outT[t][hid][b] (coalesced). Depth-4
// k-quad prefetch; next-step Xproj prefetched BEFORE the grid barrier.
#define REC_SMEM_BYTES (DIMH * 16 * 4 + 16 * 32 * 17 * 8)   // 102400

__global__ __launch_bounds__(512, 1) void lstm_kernel(
        const float* __restrict__ Wf, const float* __restrict__ Wi,
        const float* __restrict__ Wg, const float* __restrict__ Wo) {
    extern __shared__ float smem[];
    float* Whs = smem;                                                   // [512][16]
    unsigned long long* comb = (unsigned long long*)(smem + DIMH * 16);  // [16][32][17]

    const int r    = blockIdx.x;
    const int t    = threadIdx.x;
    const int w    = t >> 5;
    const int lane = t & 31;

    for (int i = t; i < DIMH * 16; i += 512) {
        int k = i >> 4;
        int cu = (i >> 2) & 3;
        int g = i & 3;
        const float* W = (g == 0) ? Wf : (g == 1) ? Wi : (g == 2) ? Wg : Wo;
        Whs[i] = W[(size_t)(DIMD + k) * DIMH + r * 4 + cu];
    }
    __syncthreads();

    float c0 = 0.0f, c1 = 0.0f;

    // prologue: xp for step 0
    float4 xpA, xpB;
    if (w < 4) {
        const float* xb = g_Xproj + (size_t)lane * N4H + r * 16 + w * 4;
        xpA = __ldg((const float4*)xb);
        xpB = __ldg((const float4*)(xb + (size_t)32 * N4H));
    }

    for (int step = 0; step < T_STEPS; ++step) {
        if (step > 0) {
            const float* __restrict__ hb = g_outT + (size_t)(step - 1) * HB + (w * 32) * BATCH;

            unsigned long long acc[16];
#pragma unroll
            for (int i = 0; i < 16; ++i) acc[i] = 0ull;

            // depth-4 prefetch: 32 h loads in flight
            float pf0[4][4], pf1[4][4];
#pragma unroll
            for (int g4 = 0; g4 < 4; ++g4)
#pragma unroll
                for (int i = 0; i < 4; ++i) {
                    pf0[g4][i] = __ldcg(hb + (g4 * 4 + i) * BATCH + lane);
                    pf1[g4][i] = __ldcg(hb + (g4 * 4 + i) * BATCH + lane + 32);
                }

#pragma unroll
            for (int qb = 0; qb < 8; ++qb) {
                float c0v[4], c1v[4];
#pragma unroll
                for (int i = 0; i < 4; ++i) { c0v[i] = pf0[qb & 3][i]; c1v[i] = pf1[qb & 3][i]; }
                if (qb < 4) {
#pragma unroll
                    for (int i = 0; i < 4; ++i) {
                        pf0[qb & 3][i] = __ldcg(hb + ((qb + 4) * 4 + i) * BATCH + lane);
                        pf1[qb & 3][i] = __ldcg(hb + ((qb + 4) * 4 + i) * BATCH + lane + 32);
                    }
                }
#pragma unroll
                for (int i = 0; i < 4; ++i) {
                    const float* wq = &Whs[(w * 32 + qb * 4 + i) * 16];
                    ULL2 wA = *(const ULL2*)(wq);
                    ULL2 wB = *(const ULL2*)(wq + 4);
                    ULL2 wC = *(const ULL2*)(wq + 8);
                    ULL2 wD = *(const ULL2*)(wq + 12);
                    unsigned long long p0 = pack2(c0v[i]);
                    unsigned long long p1 = pack2(c1v[i]);
                    acc[0]  = fma2(p0, wA.x, acc[0]);
                    acc[1]  = fma2(p0, wA.y, acc[1]);
                    acc[2]  = fma2(p0, wB.x, acc[2]);
                    acc[3]  = fma2(p0, wB.y, acc[3]);
                    acc[4]  = fma2(p0, wC.x, acc[4]);
                    acc[5]  = fma2(p0, wC.y, acc[5]);
                    acc[6]  = fma2(p0, wD.x, acc[6]);
                    acc[7]  = fma2(p0, wD.y, acc[7]);
                    acc[8]  = fma2(p1, wA.x, acc[8]);
                    acc[9]  = fma2(p1, wA.y, acc[9]);
                    acc[10] = fma2(p1, wB.x, acc[10]);
                    acc[11] = fma2(p1, wB.y, acc[11]);
                    acc[12] = fma2(p1, wC.x, acc[12]);
                    acc[13] = fma2(p1, wC.y, acc[13]);
                    acc[14] = fma2(p1, wD.x, acc[14]);
                    acc[15] = fma2(p1, wD.y, acc[15]);
                }
            }

            unsigned long long* cw = comb + ((size_t)w * 32 + lane) * 17;
#pragma unroll
            for (int i = 0; i < 16; ++i) cw[i] = acc[i];
            __syncthreads();
        }

        if (w < 4) {
            const int u = w;
            unsigned long long s0 = 0, s1 = 0, s2 = 0, s3 = 0;
            if (step > 0) {
#pragma unroll
                for (int kh = 0; kh < 16; ++kh) {
                    const unsigned long long* cr = comb + ((size_t)kh * 32 + lane) * 17;
                    s0 = add2(s0, cr[u * 2]);
                    s1 = add2(s1, cr[u * 2 + 1]);
                    s2 = add2(s2, cr[8 + u * 2]);
                    s3 = add2(s3, cr[8 + u * 2 + 1]);
                }
            }
            float zf0 = lo32(s0) + xpA.x, zi0 = hi32(s0) + xpA.y;
            float zg0 = lo32(s1) + xpA.z, zo0 = hi32(s1) + xpA.w;
            float zf1 = lo32(s2) + xpB.x, zi1 = hi32(s2) + xpB.y;
            float zg1 = lo32(s3) + xpB.z, zo1 = hi32(s3) + xpB.w;

            c0 = sigf(zf0) * c0 + sigf(zi0) * tanh_(zg0);
            c1 = sigf(zf1) * c1 + sigf(zi1) * tanh_(zg1);
            float h0v = sigf(zo0) * tanh_(c0);
            float h1v = sigf(zo1) * tanh_(c1);

            const int hid = r * 4 + u;
            float* hdst = g_outT + (size_t)step * HB + hid * BATCH;   // coalesced
            hdst[lane]      = h0v;
            hdst[lane + 32] = h1v;
            if (step == T_STEPS - 1) {
                g_cT[hid * BATCH + lane]      = c0;
                g_cT[hid * BATCH + lane + 32] = c1;
            }
            // prefetch next step's xp BEFORE the barrier (hidden behind the wait)
            if (step + 1 < T_STEPS) {
                const float* xb = g_Xproj + ((size_t)(step + 1) * BATCH + lane) * N4H + r * 16 + w * 4;
                xpA = __ldg((const float4*)xb);
                xpB = __ldg((const float4*)(xb + (size_t)32 * N4H));
            }
        }

        // ---- monotone ticket grid barrier ----
        __threadfence();
        __syncthreads();
        if (t == 0) {
            unsigned long long tk = atomicAdd(&g_tick, 1ULL);
            unsigned long long gen = tk >> 7;           // /128 CTAs
            if ((tk & 127ULL) == 127ULL) {
                __threadfence();
                g_rel = gen + 1ULL;
            } else {
                while (g_rel <= gen) { }
                __threadfence();
            }
        }
        __syncthreads();
    }
}

// ---------------- kernel 3: transpose outT -> out (+ hx/cx tail) -----------------
__global__ __launch_bounds__(256) void transpose_out(float* __restrict__ out, int out_size) {
    __shared__ float tile[32][65];
    const int tblk = blockIdx.x;         // 0..512 ; 512 == tail (hx, cx)
    const int h0   = blockIdx.y * 32;
    const int tx   = threadIdx.x;        // 0..63 (batch on load)
    const int ty   = threadIdx.y;        // 0..3
    const int tid  = ty * 64 + tx;
    const int wh   = tid & 31;
    const int wb0  = tid >> 5;

    const size_t tail = (size_t)T_STEPS * BATCH * DIMH;
    const bool write_state = (size_t)out_size >= tail + 2u * BATCH * DIMH;

    if (tblk < T_STEPS) {
        const float* src = g_outT + (size_t)tblk * HB;
#pragma unroll
        for (int i = 0; i < 8; ++i) {
            int hl = i * 4 + ty;
            tile[hl][tx] = src[(size_t)(h0 + hl) * BATCH + tx];
        }
        __syncthreads();
        float* dst = out + (size_t)tblk * BATCH * DIMH;
#pragma unroll
        for (int j = 0; j < 8; ++j) {
            int b = wb0 + j * 8;
            dst[(size_t)b * DIMH + h0 + wh] = tile[wh][b];
        }
    } else if (write_state) {
        const float* src = g_outT + (size_t)(T_STEPS - 1) * HB;
#pragma unroll
        for (int i = 0; i < 8; ++i) {
            int hl = i * 4 + ty;
            tile[hl][tx] = src[(size_t)(h0 + hl) * BATCH + tx];
        }
        __syncthreads();
        float* dst = out + tail;
#pragma unroll
        for (int j = 0; j < 8; ++j) {
            int b = wb0 + j * 8;
            dst[(size_t)b * DIMH + h0 + wh] = tile[wh][b];
        }
        __syncthreads();
#pragma unroll
        for (int i = 0; i < 8; ++i) {
            int hl = i * 4 + ty;
            tile[hl][tx] = g_cT[(size_t)(h0 + hl) * BATCH + tx];
        }
        __syncthreads();
        float* dst2 = out + tail + (size_t)BATCH * DIMH;
#pragma unroll
        for (int j = 0; j < 8; ++j) {
            int b = wb0 + j * 8;
            dst2[(size_t)b * DIMH + h0 + wh] = tile[wh][b];
        }
    }
}

// ---------------- launch ----------------------------------------------------------
extern "C" void kernel_launch(void* const* d_in, const int* in_sizes, int n_in,
                              void* d_out, int out_size) {
    const float* inputs = (const float*)d_in[0];
    const float* Wf = (const float*)d_in[1];
    const float* bf = (const float*)d_in[2];
    const float* Wi = (const float*)d_in[3];
    const float* bi = (const float*)d_in[4];
    const float* Wg = (const float*)d_in[5];
    const float* bg = (const float*)d_in[6];
    const float* Wo = (const float*)d_in[7];
    const float* bo = (const float*)d_in[8];

    dim3 g1(N4H / 64, (T_STEPS * BATCH) / 128);   // (32, 256)
    xproj_gemm<<<g1, 256>>>(inputs, Wf, bf, Wi, bi, Wg, bg, Wo, bo);

    cudaFuncSetAttribute(lstm_kernel, cudaFuncAttributeMaxDynamicSharedMemorySize, REC_SMEM_BYTES);
    lstm_kernel<<<128, 512, REC_SMEM_BYTES>>>(Wf, Wi, Wg, Wo);

    transpose_out<<<dim3(T_STEPS + 1, DIMH / 32), dim3(64, 4)>>>((float*)d_out, out_size);
}

// round 7
// speedup vs baseline: 1.6753x; 1.1590x over previous
#include <cuda_runtime.h>
#include <cuda_bf16.h>
#include <cstdint>
#include <cstddef>

#define T_STEPS 512
#define BATCH   64
#define DIMD    512
#define DIMH    512
#define N4H     2048   // 4 gates * H, packed as j' = hid*4 + gate
#define KDIM    512
#define HB      (DIMH * BATCH)
#define MROWS   (T_STEPS * BATCH)   // 32768
#define KSPLIT  1536                // 3 * 512 (bf16x3 split segments)

// ---------------- device scratch (static) ----------------------------------------
__device__ float g_Xproj[(size_t)T_STEPS * BATCH * N4H]; // 256 MB [t*B+b][j']
__device__ float g_outT[(size_t)T_STEPS * HB];           // 64 MB [t][hid][b]
__device__ float g_cT[HB];
__device__ __nv_bfloat16 g_Ap[(size_t)MROWS * KSPLIT];   // 96 MB  A' = [hi | lo | hi]
__device__ __nv_bfloat16 g_Bp[(size_t)N4H * KSPLIT];     // 6 MB   B'[j'][k] = [hi | hi | lo]
__device__ unsigned long long g_tick = 0ULL;
__device__ volatile unsigned long long g_rel = 0ULL;

// ---------------- f32x2 helpers ---------------------------------------------------
struct __align__(16) ULL2 { unsigned long long x, y; };

static __device__ __forceinline__ unsigned long long pack2(float v) {
    unsigned long long r;
    unsigned u = __float_as_uint(v);
    asm("mov.b64 %0, {%1, %2};" : "=l"(r) : "r"(u), "r"(u));
    return r;
}
static __device__ __forceinline__ unsigned long long fma2(unsigned long long a,
                                                          unsigned long long b,
                                                          unsigned long long c) {
    unsigned long long d;
    asm("fma.rn.f32x2 %0, %1, %2, %3;" : "=l"(d) : "l"(a), "l"(b), "l"(c));
    return d;
}
static __device__ __forceinline__ unsigned long long add2(unsigned long long a,
                                                          unsigned long long b) {
    unsigned long long d;
    asm("add.rn.f32x2 %0, %1, %2;" : "=l"(d) : "l"(a), "l"(b));
    return d;
}
static __device__ __forceinline__ float lo32(unsigned long long v) {
    return __uint_as_float((unsigned)(v & 0xffffffffull));
}
static __device__ __forceinline__ float hi32(unsigned long long v) {
    return __uint_as_float((unsigned)(v >> 32));
}
static __device__ __forceinline__ float sigf(float x) {
    return __fdividef(1.0f, 1.0f + __expf(-x));
}
static __device__ __forceinline__ float tanh_(float x) {
    return 2.0f * sigf(2.0f * x) - 1.0f;
}

// ---------------- pack kernels (bf16 hi/lo split) ---------------------------------
__global__ void pack_a(const float* __restrict__ X) {
    size_t idx = (size_t)blockIdx.x * blockDim.x + threadIdx.x;
    size_t stride = (size_t)gridDim.x * blockDim.x;
    for (size_t i = idx; i < (size_t)MROWS * KDIM; i += stride) {
        size_t m = i / KDIM, k = i % KDIM;
        float x = X[i];
        __nv_bfloat16 hi = __float2bfloat16(x);
        __nv_bfloat16 lo = __float2bfloat16(x - __bfloat162float(hi));
        __nv_bfloat16* row = g_Ap + m * KSPLIT;
        row[k] = hi; row[512 + k] = lo; row[1024 + k] = hi;
    }
}
__global__ void pack_b(const float* __restrict__ Wf, const float* __restrict__ Wi,
                       const float* __restrict__ Wg, const float* __restrict__ Wo) {
    size_t idx = (size_t)blockIdx.x * blockDim.x + threadIdx.x;
    size_t stride = (size_t)gridDim.x * blockDim.x;
    for (size_t i = idx; i < (size_t)N4H * KDIM; i += stride) {
        size_t j = i / KDIM, k = i % KDIM;
        int g = (int)(j & 3), c = (int)(j >> 2);
        const float* W = (g == 0) ? Wf : (g == 1) ? Wi : (g == 2) ? Wg : Wo;
        float w = W[k * DIMH + c];
        __nv_bfloat16 hi = __float2bfloat16(w);
        __nv_bfloat16 lo = __float2bfloat16(w - __bfloat162float(hi));
        __nv_bfloat16* row = g_Bp + j * KSPLIT;
        row[k] = hi; row[512 + k] = hi; row[1024 + k] = lo;
    }
}

// ---------------- kernel: xproj GEMM via mma.sync (bf16x3, fp32 accum) ------------
// C[32768,2048] = A'[32768,1536] @ B'^T ; BM=128, BN=128, BK=32, 256 thr (8 warps).
// Warp grid 2(m) x 4(n); warp tile 64m x 32n; m16n8k16 HMMA.
#define XBM 128
#define XBN 128
#define XBK 32
#define XROWS 40     // smem row stride in bf16 (32 data + 8 pad -> 80B, 16B-aligned)

static __device__ __forceinline__ uint32_t smem_u32(const void* p) {
    uint32_t a;
    asm("{ .reg .u64 t; cvta.to.shared.u64 t, %1; cvt.u32.u64 %0, t; }" : "=r"(a) : "l"(p));
    return a;
}
static __device__ __forceinline__ void ldsm_x4(uint32_t* r, uint32_t addr) {
    asm volatile("ldmatrix.sync.aligned.m8n8.x4.shared.b16 {%0,%1,%2,%3}, [%4];"
                 : "=r"(r[0]), "=r"(r[1]), "=r"(r[2]), "=r"(r[3]) : "r"(addr));
}
static __device__ __forceinline__ void hmma16816(float* c, const uint32_t* a,
                                                 uint32_t b0, uint32_t b1) {
    asm volatile("mma.sync.aligned.m16n8k16.row.col.f32.bf16.bf16.f32 "
                 "{%0,%1,%2,%3}, {%4,%5,%6,%7}, {%8,%9}, {%0,%1,%2,%3};"
                 : "+f"(c[0]), "+f"(c[1]), "+f"(c[2]), "+f"(c[3])
                 : "r"(a[0]), "r"(a[1]), "r"(a[2]), "r"(a[3]), "r"(b0), "r"(b1));
}

__global__ __launch_bounds__(256) void xproj_mma(
        const float* __restrict__ bf, const float* __restrict__ bi,
        const float* __restrict__ bg, const float* __restrict__ bo) {
    __shared__ __nv_bfloat16 As[2][XBM * XROWS];
    __shared__ __nv_bfloat16 Bs[2][XBN * XROWS];
    __shared__ float bsm[XBN];

    const int tid  = threadIdx.x;
    const int wid  = tid >> 5;
    const int lane = tid & 31;
    const int wm   = wid & 1;      // 0..1
    const int wn   = wid >> 1;     // 0..3
    const int m0   = blockIdx.y * XBM;
    const int n0   = blockIdx.x * XBN;

    // bias stage
    if (tid < XBN) {
        int j = n0 + tid, g = j & 3, c = j >> 2;
        bsm[tid] = (g == 0 ? bf : g == 1 ? bi : g == 2 ? bg : bo)[c];
    }

    float acc[4][4][4];
#pragma unroll
    for (int a = 0; a < 4; ++a)
#pragma unroll
        for (int b = 0; b < 4; ++b)
#pragma unroll
            for (int q = 0; q < 4; ++q) acc[a][b][q] = 0.0f;

    // loader mapping: thread -> row (tid>>1), k-half (tid&1)*16
    const int lrow = tid >> 1;
    const int lofs = (tid & 1) * 16;
    const __nv_bfloat16* asrc = g_Ap + (size_t)(m0 + lrow) * KSPLIT + lofs;
    const __nv_bfloat16* bsrc = g_Bp + (size_t)(n0 + lrow) * KSPLIT + lofs;
    const int sidx = lrow * XROWS + lofs;

    // ldmatrix per-thread address components
    const int a_row = wm * 64 + (lane & 7) + ((lane >> 3) & 1) * 8;   // + mt*16
    const int a_col = ((lane >> 4) & 1) * 8;                          // + k16*16
    const int b_row = wn * 32 + (lane & 7) + ((lane >> 4) & 1) * 8;   // + half*16
    const int b_col = ((lane >> 3) & 1) * 8;                          // + k16*16
    const uint32_t As0 = smem_u32(&As[0][0]);
    const uint32_t Bs0 = smem_u32(&Bs[0][0]);
    const uint32_t BUFA = XBM * XROWS * 2;   // bytes per A buffer
    const uint32_t BUFB = XBN * XROWS * 2;

    // prologue: tile 0
    uint4 a0v = *(const uint4*)(asrc);
    uint4 a1v = *(const uint4*)(asrc + 8);
    uint4 b0v = *(const uint4*)(bsrc);
    uint4 b1v = *(const uint4*)(bsrc + 8);
    *(uint4*)&As[0][sidx]     = a0v;
    *(uint4*)&As[0][sidx + 8] = a1v;
    *(uint4*)&Bs[0][sidx]     = b0v;
    *(uint4*)&Bs[0][sidx + 8] = b1v;
    __syncthreads();

    int p = 0;
    const int NIT = KSPLIT / XBK;   // 48
    for (int it = 0; it < NIT; ++it) {
        const bool more = (it + 1) < NIT;
        if (more) {
            a0v = *(const uint4*)(asrc + (it + 1) * XBK);
            a1v = *(const uint4*)(asrc + (it + 1) * XBK + 8);
            b0v = *(const uint4*)(bsrc + (it + 1) * XBK);
            b1v = *(const uint4*)(bsrc + (it + 1) * XBK + 8);
        }

#pragma unroll
        for (int k16 = 0; k16 < 2; ++k16) {
            uint32_t af[4][4];
#pragma unroll
            for (int mt = 0; mt < 4; ++mt) {
                uint32_t addr = As0 + p * BUFA
                              + (uint32_t)(((a_row + mt * 16) * XROWS + k16 * 16 + a_col) * 2);
                ldsm_x4(af[mt], addr);
            }
            uint32_t bg2[2][4];
#pragma unroll
            for (int hf = 0; hf < 2; ++hf) {
                uint32_t addr = Bs0 + p * BUFB
                              + (uint32_t)(((b_row + hf * 16) * XROWS + k16 * 16 + b_col) * 2);
                ldsm_x4(bg2[hf], addr);
            }
#pragma unroll
            for (int mt = 0; mt < 4; ++mt)
#pragma unroll
                for (int nt = 0; nt < 4; ++nt)
                    hmma16816(acc[mt][nt], af[mt],
                              bg2[nt >> 1][(nt & 1) * 2], bg2[nt >> 1][(nt & 1) * 2 + 1]);
        }

        if (more) {
            *(uint4*)&As[p ^ 1][sidx]     = a0v;
            *(uint4*)&As[p ^ 1][sidx + 8] = a1v;
            *(uint4*)&Bs[p ^ 1][sidx]     = b0v;
            *(uint4*)&Bs[p ^ 1][sidx + 8] = b1v;
            __syncthreads();
        }
        p ^= 1;
    }

    // epilogue: c frag (row=lane>>2 / +8, col=(lane&3)*2)
#pragma unroll
    for (int mt = 0; mt < 4; ++mt) {
#pragma unroll
        for (int nt = 0; nt < 4; ++nt) {
            int row = m0 + wm * 64 + mt * 16 + (lane >> 2);
            int cl  = wn * 32 + nt * 8 + (lane & 3) * 2;   // local col
            float2 v0 = { acc[mt][nt][0] + bsm[cl], acc[mt][nt][1] + bsm[cl + 1] };
            float2 v1 = { acc[mt][nt][2] + bsm[cl], acc[mt][nt][3] + bsm[cl + 1] };
            *(float2*)&g_Xproj[(size_t)row * N4H + n0 + cl]       = v0;
            *(float2*)&g_Xproj[(size_t)(row + 8) * N4H + n0 + cl] = v1;
        }
    }
}

// ---------------- kernel: persistent recurrence (v6) ------------------------------
// 128 CTAs x 512 threads. CTA r: hidden units [r*4,+4). Warp w: k-slice [w*32,+32).
// Thread (w,lane): batches 2*lane, 2*lane+1 (float2 h loads). Tail: 256 threads,
// one (u=t>>6, b=t&63) output each. Ticket grid barrier.
#define REC_SMEM_BYTES (DIMH * 16 * 4 + 16 * 32 * 17 * 8)   // 102400

__global__ __launch_bounds__(512, 1) void lstm_kernel(
        const float* __restrict__ Wf, const float* __restrict__ Wi,
        const float* __restrict__ Wg, const float* __restrict__ Wo) {
    extern __shared__ float smem[];
    float* Whs = smem;                                                   // [512][16]
    unsigned long long* comb = (unsigned long long*)(smem + DIMH * 16);  // [16*32][17]

    const int r    = blockIdx.x;
    const int t    = threadIdx.x;
    const int w    = t >> 5;
    const int lane = t & 31;
    const int u    = t >> 6;       // tail: unit (t<256)
    const int b    = t & 63;       // tail: batch

    for (int i = t; i < DIMH * 16; i += 512) {
        int k = i >> 4;
        int cu = (i >> 2) & 3;
        int g = i & 3;
        const float* W = (g == 0) ? Wf : (g == 1) ? Wi : (g == 2) ? Wg : Wo;
        Whs[i] = W[(size_t)(DIMD + k) * DIMH + r * 4 + cu];
    }
    __syncthreads();

    float cst = 0.0f;    // cell state for tail threads

    float4 xpA;
    if (t < 256) {
        xpA = __ldg((const float4*)(g_Xproj + (size_t)b * N4H + r * 16 + u * 4));
    }

    for (int step = 0; step < T_STEPS; ++step) {
        if (step > 0) {
            const float* __restrict__ hb = g_outT + (size_t)(step - 1) * HB
                                         + (w * 32) * BATCH + lane * 2;

            unsigned long long acc[16];
#pragma unroll
            for (int i = 0; i < 16; ++i) acc[i] = 0ull;

            float2 pf[4][4];
#pragma unroll
            for (int g4 = 0; g4 < 4; ++g4)
#pragma unroll
                for (int i = 0; i < 4; ++i)
                    pf[g4][i] = __ldcg((const float2*)(hb + (g4 * 4 + i) * BATCH));

#pragma unroll
            for (int qb = 0; qb < 8; ++qb) {
                float2 cv[4];
#pragma unroll
                for (int i = 0; i < 4; ++i) cv[i] = pf[qb & 3][i];
                if (qb < 4) {
#pragma unroll
                    for (int i = 0; i < 4; ++i)
                        pf[qb & 3][i] = __ldcg((const float2*)(hb + ((qb + 4) * 4 + i) * BATCH));
                }
#pragma unroll
                for (int i = 0; i < 4; ++i) {
                    const float* wq = &Whs[(w * 32 + qb * 4 + i) * 16];
                    ULL2 wA = *(const ULL2*)(wq);
                    ULL2 wB = *(const ULL2*)(wq + 4);
                    ULL2 wC = *(const ULL2*)(wq + 8);
                    ULL2 wD = *(const ULL2*)(wq + 12);
                    unsigned long long p0 = pack2(cv[i].x);
                    unsigned long long p1 = pack2(cv[i].y);
                    acc[0]  = fma2(p0, wA.x, acc[0]);
                    acc[1]  = fma2(p0, wA.y, acc[1]);
                    acc[2]  = fma2(p0, wB.x, acc[2]);
                    acc[3]  = fma2(p0, wB.y, acc[3]);
                    acc[4]  = fma2(p0, wC.x, acc[4]);
                    acc[5]  = fma2(p0, wC.y, acc[5]);
                    acc[6]  = fma2(p0, wD.x, acc[6]);
                    acc[7]  = fma2(p0, wD.y, acc[7]);
                    acc[8]  = fma2(p1, wA.x, acc[8]);
                    acc[9]  = fma2(p1, wA.y, acc[9]);
                    acc[10] = fma2(p1, wB.x, acc[10]);
                    acc[11] = fma2(p1, wB.y, acc[11]);
                    acc[12] = fma2(p1, wC.x, acc[12]);
                    acc[13] = fma2(p1, wC.y, acc[13]);
                    acc[14] = fma2(p1, wD.x, acc[14]);
                    acc[15] = fma2(p1, wD.y, acc[15]);
                }
            }

            unsigned long long* cw = comb + ((size_t)w * 32 + lane) * 17;
#pragma unroll
            for (int i = 0; i < 16; ++i) cw[i] = acc[i];
            __syncthreads();
        }

        if (t < 256) {
            unsigned long long s0 = 0, s1 = 0;
            if (step > 0) {
#pragma unroll
                for (int kh = 0; kh < 16; ++kh) {
                    const unsigned long long* cr =
                        comb + ((size_t)kh * 32 + (b >> 1)) * 17 + (b & 1) * 8;
                    s0 = add2(s0, cr[u * 2]);
                    s1 = add2(s1, cr[u * 2 + 1]);
                }
            }
            float zf = lo32(s0) + xpA.x, zi = hi32(s0) + xpA.y;
            float zg = lo32(s1) + xpA.z, zo = hi32(s1) + xpA.w;

            cst = sigf(zf) * cst + sigf(zi) * tanh_(zg);
            float hv = sigf(zo) * tanh_(cst);

            const int hid = r * 4 + u;
            g_outT[(size_t)step * HB + hid * BATCH + b] = hv;
            if (step == T_STEPS - 1) g_cT[hid * BATCH + b] = cst;
            if (step + 1 < T_STEPS) {
                xpA = __ldg((const float4*)(g_Xproj
                        + ((size_t)(step + 1) * BATCH + b) * N4H + r * 16 + u * 4));
            }
        }

        // ---- monotone ticket grid barrier ----
        __threadfence();
        __syncthreads();
        if (t == 0) {
            unsigned long long tk = atomicAdd(&g_tick, 1ULL);
            unsigned long long gen = tk >> 7;
            if ((tk & 127ULL) == 127ULL) {
                __threadfence();
                g_rel = gen + 1ULL;
            } else {
                while (g_rel <= gen) { }
                __threadfence();
            }
        }
        __syncthreads();
    }
}

// ---------------- transpose outT -> out (+ hx/cx tail) ----------------------------
__global__ __launch_bounds__(256) void transpose_out(float* __restrict__ out, int out_size) {
    __shared__ float tile[32][65];
    const int tblk = blockIdx.x;
    const int h0   = blockIdx.y * 32;
    const int tx   = threadIdx.x;
    const int ty   = threadIdx.y;
    const int tid  = ty * 64 + tx;
    const int wh   = tid & 31;
    const int wb0  = tid >> 5;

    const size_t tail = (size_t)T_STEPS * BATCH * DIMH;
    const bool write_state = (size_t)out_size >= tail + 2u * BATCH * DIMH;

    if (tblk < T_STEPS) {
        const float* src = g_outT + (size_t)tblk * HB;
#pragma unroll
        for (int i = 0; i < 8; ++i) {
            int hl = i * 4 + ty;
            tile[hl][tx] = src[(size_t)(h0 + hl) * BATCH + tx];
        }
        __syncthreads();
        float* dst = out + (size_t)tblk * BATCH * DIMH;
#pragma unroll
        for (int j = 0; j < 8; ++j) {
            int bb = wb0 + j * 8;
            dst[(size_t)bb * DIMH + h0 + wh] = tile[wh][bb];
        }
    } else if (write_state) {
        const float* src = g_outT + (size_t)(T_STEPS - 1) * HB;
#pragma unroll
        for (int i = 0; i < 8; ++i) {
            int hl = i * 4 + ty;
            tile[hl][tx] = src[(size_t)(h0 + hl) * BATCH + tx];
        }
        __syncthreads();
        float* dst = out + tail;
#pragma unroll
        for (int j = 0; j < 8; ++j) {
            int bb = wb0 + j * 8;
            dst[(size_t)bb * DIMH + h0 + wh] = tile[wh][bb];
        }
        __syncthreads();
#pragma unroll
        for (int i = 0; i < 8; ++i) {
            int hl = i * 4 + ty;
            tile[hl][tx] = g_cT[(size_t)(h0 + hl) * BATCH + tx];
        }
        __syncthreads();
        float* dst2 = out + tail + (size_t)BATCH * DIMH;
#pragma unroll
        for (int j = 0; j < 8; ++j) {
            int bb = wb0 + j * 8;
            dst2[(size_t)bb * DIMH + h0 + wh] = tile[wh][bb];
        }
    }
}

// ---------------- launch ----------------------------------------------------------
extern "C" void kernel_launch(void* const* d_in, const int* in_sizes, int n_in,
                              void* d_out, int out_size) {
    const float* inputs = (const float*)d_in[0];
    const float* Wf = (const float*)d_in[1];
    const float* bf = (const float*)d_in[2];
    const float* Wi = (const float*)d_in[3];
    const float* bi = (const float*)d_in[4];
    const float* Wg = (const float*)d_in[5];
    const float* bg = (const float*)d_in[6];
    const float* Wo = (const float*)d_in[7];
    const float* bo = (const float*)d_in[8];

    pack_a<<<1024, 256>>>(inputs);
    pack_b<<<256, 256>>>(Wf, Wi, Wg, Wo);

    dim3 gx(N4H / XBN, MROWS / XBM);   // (16, 256)
    xproj_mma<<<gx, 256>>>(bf, bi, bg, bo);

    cudaFuncSetAttribute(lstm_kernel, cudaFuncAttributeMaxDynamicSharedMemorySize, REC_SMEM_BYTES);
    lstm_kernel<<<128, 512, REC_SMEM_BYTES>>>(Wf, Wi, Wg, Wo);

    transpose_out<<<dim3(T_STEPS + 1, DIMH / 32), dim3(64, 4)>>>((float*)d_out, out_size);
}